// round 9
// baseline (speedup 1.0000x reference)
#include <cuda_runtime.h>
#include <math.h>
#include <stdint.h>

// Problem constants
#define D_M   1024
#define B_N   4
#define T_N   2048
#define H_N   16
#define HS_N  64
#define MROWS (B_N * T_N)   // 8192
#define CH_L  32            // chunk length
#define CH_N  (T_N / CH_L)  // 64 chunks
#define BH_N  (B_N * H_N)   // 64

#define WM_SZ ((size_t)D_M * D_M)   // 1M floats

// GEMM dynamic smem: As[2][128][36] + Bs[2][32][136]
#define GEMM_SMEM_FLOATS (2 * 128 * 36 + 2 * 32 * 136)
#define GEMM_SMEM_BYTES  (GEMM_SMEM_FLOATS * 4)   // 71680

// ---------------------------------------------------------------------------
// Scratch (static device globals)
// ---------------------------------------------------------------------------
__device__ float g_xn[(size_t)MROWS * D_M];
__device__ float g_w [(size_t)MROWS * D_M];
__device__ float g_k [(size_t)MROWS * D_M];
__device__ float g_v [(size_t)MROWS * D_M];
__device__ float g_r [(size_t)MROWS * D_M];   // becomes q after pass A
__device__ float g_o [(size_t)MROWS * D_M];
// weight pool: [0..4M) packed [Wk|Wv|Wr|Wc] (row stride 4096)
//              [4M..5M) Wx_r  [5M..6M) Ww_r  [6M..7M) Wo_r (stride 1024)
__device__ float g_wt[(size_t)7 * WM_SZ];
__device__ float g_wcp[(size_t)4 * WM_SZ];                  // Wc split-K partials
__device__ float g_sloc[(size_t)BH_N * CH_N * HS_N * HS_N]; // [bh][ch][e][d]
__device__ float g_sin [(size_t)BH_N * CH_N * HS_N * HS_N]; // [bh][ch][e][d]
__device__ float g_pc  [(size_t)BH_N * CH_N * HS_N];        // [bh][ch][d]

enum Buf { BUF_XN = 0, BUF_O, BUF_EXT };

template <int B> __device__ __forceinline__ float* buf_ptr(float* ext) {
    if (B == BUF_XN)   return g_xn;
    if (B == BUF_O)    return g_o;
    return ext;
}

// ---------------------------------------------------------------------------
// PTX helpers
// ---------------------------------------------------------------------------
__device__ __forceinline__ void cp16(void* smem_dst, const void* gsrc) {
    uint32_t s = (uint32_t)__cvta_generic_to_shared(smem_dst);
    asm volatile("cp.async.cg.shared.global [%0], [%1], 16;\n" :: "r"(s), "l"(gsrc));
}
#define CP_COMMIT() asm volatile("cp.async.commit_group;\n" ::: "memory")
template <int N> __device__ __forceinline__ void cp_wait() {
    asm volatile("cp.async.wait_group %0;\n" :: "n"(N) : "memory");
}
__device__ __forceinline__ float to_tf32f(float x) {
    uint32_t r;
    asm("cvt.rna.tf32.f32 %0, %1;\n" : "=r"(r) : "f"(x));
    return __uint_as_float(r);
}
__device__ __forceinline__ float4 rnd4(float4 v) {
    v.x = to_tf32f(v.x); v.y = to_tf32f(v.y);
    v.z = to_tf32f(v.z); v.w = to_tf32f(v.w);
    return v;
}
__device__ __forceinline__ void mma_tf32(float* c, const uint32_t* a, const uint32_t* b) {
    asm volatile(
        "mma.sync.aligned.m16n8k8.row.col.f32.tf32.tf32.f32 "
        "{%0,%1,%2,%3}, {%4,%5,%6,%7}, {%8,%9}, {%0,%1,%2,%3};\n"
        : "+f"(c[0]), "+f"(c[1]), "+f"(c[2]), "+f"(c[3])
        : "r"(a[0]), "r"(a[1]), "r"(a[2]), "r"(a[3]), "r"(b[0]), "r"(b[1]));
}

// ---------------------------------------------------------------------------
// round_w: tf32-round all weights. Wk,Wv,Wr -> packed slots 0..2;
// Wx -> +4M, Ww -> +5M, Wo -> +6M. grid 1024 x 256.
// ---------------------------------------------------------------------------
__global__ __launch_bounds__(256) void round_w_kernel(
    const float* __restrict__ Wx, const float* __restrict__ Ww,
    const float* __restrict__ Wk, const float* __restrict__ Wv,
    const float* __restrict__ Wr, const float* __restrict__ Wo)
{
    size_t idx = ((size_t)blockIdx.x * 256 + threadIdx.x) * 4;  // 0..1M step 4
    size_t k = idx >> 10, c = idx & 1023;

    *(float4*)(g_wt + k * 4096 + 0 * D_M + c) = rnd4(*(const float4*)(Wk + idx));
    *(float4*)(g_wt + k * 4096 + 1 * D_M + c) = rnd4(*(const float4*)(Wv + idx));
    *(float4*)(g_wt + k * 4096 + 2 * D_M + c) = rnd4(*(const float4*)(Wr + idx));
    *(float4*)(g_wt + 4 * WM_SZ + idx) = rnd4(*(const float4*)(Wx + idx));
    *(float4*)(g_wt + 5 * WM_SZ + idx) = rnd4(*(const float4*)(Ww + idx));
    *(float4*)(g_wt + 6 * WM_SZ + idx) = rnd4(*(const float4*)(Wo + idx));
}

// ---------------------------------------------------------------------------
// LayerNorm -> g_xn (tf32-rounded)
// ---------------------------------------------------------------------------
__global__ __launch_bounds__(256) void ln_kernel(
    const float* __restrict__ X, const float* __restrict__ G,
    const float* __restrict__ Bv)
{
    __shared__ float red[16];
    int row = blockIdx.x;
    int tid = threadIdx.x;
    const float* xr = X + (size_t)row * D_M;

    float4 xv = *(const float4*)(xr + tid * 4);
    float s = xv.x + xv.y + xv.z + xv.w;
    float q = xv.x * xv.x + xv.y * xv.y + xv.z * xv.z + xv.w * xv.w;

    #pragma unroll
    for (int o = 16; o > 0; o >>= 1) {
        s += __shfl_xor_sync(0xffffffffu, s, o);
        q += __shfl_xor_sync(0xffffffffu, q, o);
    }
    int wid = tid >> 5, lid = tid & 31;
    if (lid == 0) { red[wid] = s; red[8 + wid] = q; }
    __syncthreads();
    if (wid == 0) {
        float s2 = (lid < 8) ? red[lid] : 0.f;
        float q2 = (lid < 8) ? red[8 + lid] : 0.f;
        #pragma unroll
        for (int o = 4; o > 0; o >>= 1) {
            s2 += __shfl_xor_sync(0xffffffffu, s2, o);
            q2 += __shfl_xor_sync(0xffffffffu, q2, o);
        }
        if (lid == 0) { red[0] = s2; red[1] = q2; }
    }
    __syncthreads();

    float mu   = red[0] * (1.f / D_M);
    float var  = red[1] * (1.f / D_M) - mu * mu;
    float rstd = rsqrtf(var + 1e-5f);

    float4 gv = *(const float4*)(G + tid * 4);
    float4 bv = *(const float4*)(Bv + tid * 4);
    float4 yv;
    yv.x = to_tf32f((xv.x - mu) * rstd * gv.x + bv.x);
    yv.y = to_tf32f((xv.y - mu) * rstd * gv.y + bv.y);
    yv.z = to_tf32f((xv.z - mu) * rstd * gv.z + bv.z);
    yv.w = to_tf32f((xv.w - mu) * rstd * gv.w + bv.w);
    *(float4*)(g_xn + (size_t)row * D_M + tid * 4) = yv;
}

// ---------------------------------------------------------------------------
// GEMM core, BK=32: one 128x128 tile over K range [kbeg, kend).
// 2-stage cp.async, 4 warps, warp tile 64x64. Dynamic smem:
//   As[2][128][36] then Bs[2][32][136].
// ---------------------------------------------------------------------------
template <int WS>
__device__ __forceinline__ void gemm_tile32(
    const float* __restrict__ A, const float* __restrict__ Wm,
    int bm, int bn, int tid, float acc[4][8][4],
    float (*As)[128][36], float (*Bs)[32][136],
    int kbeg, int kend)
{
    auto load_stage = [&](int buf, int k0) {
        #pragma unroll
        for (int j = 0; j < 8; j++) {
            int f   = tid + j * 128;          // 0..1023
            int row = f >> 3;
            int kc  = (f & 7) << 2;
            cp16(&As[buf][row][kc], A + (size_t)(bm + row) * D_M + k0 + kc);
        }
        #pragma unroll
        for (int j = 0; j < 8; j++) {
            int f  = tid + j * 128;
            int kr = f >> 5;                  // 0..31
            int nc = (f & 31) << 2;
            cp16(&Bs[buf][kr][nc], Wm + (size_t)(k0 + kr) * WS + bn + nc);
        }
        CP_COMMIT();
    };

    int wid = tid >> 5, lane = tid & 31;
    int g = lane >> 2, cq = lane & 3;
    int wm = (wid & 1) * 64, wn = (wid >> 1) * 64;
    int nkt = (kend - kbeg) >> 5;

    load_stage(0, kbeg);

    for (int kt = 0; kt < nkt; kt++) {
        int buf = kt & 1;
        if (kt < nkt - 1) {
            load_stage(buf ^ 1, kbeg + (kt + 1) * 32);
            cp_wait<1>();
        } else {
            cp_wait<0>();
        }
        __syncthreads();

        #pragma unroll
        for (int ks = 0; ks < 4; ks++) {
            uint32_t af[4][4], bf[8][2];
            #pragma unroll
            for (int mi = 0; mi < 4; mi++) {
                int r0 = wm + mi * 16 + g;
                af[mi][0] = *(const uint32_t*)&As[buf][r0    ][ks * 8 + cq];
                af[mi][1] = *(const uint32_t*)&As[buf][r0 + 8][ks * 8 + cq];
                af[mi][2] = *(const uint32_t*)&As[buf][r0    ][ks * 8 + cq + 4];
                af[mi][3] = *(const uint32_t*)&As[buf][r0 + 8][ks * 8 + cq + 4];
            }
            #pragma unroll
            for (int ni = 0; ni < 8; ni++) {
                int c0 = wn + ni * 8 + g;
                bf[ni][0] = *(const uint32_t*)&Bs[buf][ks * 8 + cq    ][c0];
                bf[ni][1] = *(const uint32_t*)&Bs[buf][ks * 8 + cq + 4][c0];
            }
            #pragma unroll
            for (int mi = 0; mi < 4; mi++)
                #pragma unroll
                for (int ni = 0; ni < 8; ni++)
                    mma_tf32(acc[mi][ni], af[mi], bf[ni]);
        }
        __syncthreads();
    }
}

#define GEMM_SMEM_SETUP() \
    extern __shared__ float dsm[]; \
    float (*As)[128][36] = reinterpret_cast<float(*)[128][36]>(dsm); \
    float (*Bs)[32][136] = reinterpret_cast<float(*)[32][136]>(dsm + 2 * 128 * 36)

#define ACC_INIT(acc) \
    _Pragma("unroll") \
    for (int mi = 0; mi < 4; mi++) \
        _Pragma("unroll") \
        for (int ni = 0; ni < 8; ni++) \
            _Pragma("unroll") \
            for (int x = 0; x < 4; x++) acc[mi][ni][x] = 0.f

// ---------------------------------------------------------------------------
// Generic GEMM: C = act(A @ W); W at g_wt+WOFF*1M (stride 1024),
// C row stride CS. FLAGS: bit0 sigmoid, bit2 round.
// ---------------------------------------------------------------------------
template <int ASEL, int CSEL, int WOFF, int COFF, int CS, int FLAGS>
__global__ __launch_bounds__(128, 3) void gemm_tc(float* __restrict__ Cext)
{
    GEMM_SMEM_SETUP();

    const float* A  = buf_ptr<ASEL>(nullptr);
    const float* Wm = g_wt + (size_t)WOFF * WM_SZ;
    float*       C  = buf_ptr<CSEL>(Cext) + COFF;

    int tid = threadIdx.x;
    int bm = blockIdx.y * 128, bn = blockIdx.x * 128;

    float acc[4][8][4];
    ACC_INIT(acc);

    gemm_tile32<D_M>(A, Wm, bm, bn, tid, acc, As, Bs, 0, D_M);

    int wid = tid >> 5, lane = tid & 31;
    int g = lane >> 2, cq = lane & 3;
    int wm = (wid & 1) * 64, wn = (wid >> 1) * 64;

    #pragma unroll
    for (int mi = 0; mi < 4; mi++) {
        int row0 = bm + wm + mi * 16 + g;
        #pragma unroll
        for (int ni = 0; ni < 8; ni++) {
            int col = bn + wn + ni * 8 + cq * 2;
            float v0 = acc[mi][ni][0];
            float v1 = acc[mi][ni][1];
            float v2 = acc[mi][ni][2];
            float v3 = acc[mi][ni][3];
            if (FLAGS & 1) {
                v0 = 1.f / (1.f + expf(-v0));
                v1 = 1.f / (1.f + expf(-v1));
                v2 = 1.f / (1.f + expf(-v2));
                v3 = 1.f / (1.f + expf(-v3));
            }
            if (FLAGS & 4) {
                v0 = to_tf32f(v0); v1 = to_tf32f(v1);
                v2 = to_tf32f(v2); v3 = to_tf32f(v3);
            }
            *(float2*)(C + (size_t)row0 * CS + col)       = make_float2(v0, v1);
            *(float2*)(C + (size_t)(row0 + 8) * CS + col) = make_float2(v2, v3);
        }
    }
}

// ---------------------------------------------------------------------------
// Wc split-K partial: g_wcp[z] = Wx_r @ Ww_r over K slice z*256..z*256+256.
// grid (8, 8, 4).
// ---------------------------------------------------------------------------
__global__ __launch_bounds__(128, 3) void gemm_wc(void)
{
    GEMM_SMEM_SETUP();

    const float* A  = g_wt + 4 * WM_SZ;   // Wx_r
    const float* Wm = g_wt + 5 * WM_SZ;   // Ww_r
    float*       C  = g_wcp + (size_t)blockIdx.z * WM_SZ;

    int tid = threadIdx.x;
    int bm = blockIdx.y * 128, bn = blockIdx.x * 128;
    int kbeg = blockIdx.z * 256;

    float acc[4][8][4];
    ACC_INIT(acc);

    gemm_tile32<D_M>(A, Wm, bm, bn, tid, acc, As, Bs, kbeg, kbeg + 256);

    int wid = tid >> 5, lane = tid & 31;
    int g = lane >> 2, cq = lane & 3;
    int wm = (wid & 1) * 64, wn = (wid >> 1) * 64;

    #pragma unroll
    for (int mi = 0; mi < 4; mi++) {
        int row0 = bm + wm + mi * 16 + g;
        #pragma unroll
        for (int ni = 0; ni < 8; ni++) {
            int col = bn + wn + ni * 8 + cq * 2;
            *(float2*)(C + (size_t)row0 * D_M + col)       = make_float2(acc[mi][ni][0], acc[mi][ni][1]);
            *(float2*)(C + (size_t)(row0 + 8) * D_M + col) = make_float2(acc[mi][ni][2], acc[mi][ni][3]);
        }
    }
}

// ---------------------------------------------------------------------------
// Wc reduce: sum 4 partials, round, write packed slab 3. grid 1024 x 256.
// ---------------------------------------------------------------------------
__global__ __launch_bounds__(256) void wc_reduce(void)
{
    size_t idx = ((size_t)blockIdx.x * 256 + threadIdx.x) * 4;
    size_t k = idx >> 10, c = idx & 1023;

    float4 a = *(const float4*)(g_wcp + idx);
    float4 b = *(const float4*)(g_wcp + WM_SZ + idx);
    float4 d = *(const float4*)(g_wcp + 2 * WM_SZ + idx);
    float4 e = *(const float4*)(g_wcp + 3 * WM_SZ + idx);
    float4 s;
    s.x = a.x + b.x + d.x + e.x;
    s.y = a.y + b.y + d.y + e.y;
    s.z = a.z + b.z + d.z + e.z;
    s.w = a.w + b.w + d.w + e.w;
    *(float4*)(g_wt + k * 4096 + 3 * D_M + c) = rnd4(s);
}

// ---------------------------------------------------------------------------
// Fused projection GEMM: xn[8192][1024] @ packed[1024][4096].
// n-slab 0 -> g_k, 1 -> g_v, 2 -> sigmoid -> g_r, 3 -> sigmoid(+bw) -> g_w.
// grid (32, 64).
// ---------------------------------------------------------------------------
__global__ __launch_bounds__(128, 3) void gemm_fused(const float* __restrict__ bw)
{
    GEMM_SMEM_SETUP();

    int tid = threadIdx.x;
    int bm = blockIdx.y * 128, bn = blockIdx.x * 128;

    float acc[4][8][4];
    ACC_INIT(acc);

    gemm_tile32<4096>(g_xn, g_wt, bm, bn, tid, acc, As, Bs, 0, D_M);

    int wid = tid >> 5, lane = tid & 31;
    int g = lane >> 2, cq = lane & 3;
    int wm = (wid & 1) * 64, wn = (wid >> 1) * 64;

    int nb = bn >> 10;          // slab
    int nc0 = bn & 1023;        // local col base
    float* dest = (nb == 0) ? g_k : (nb == 1) ? g_v : (nb == 2) ? g_r : g_w;
    bool sig = (nb >= 2);
    bool hasb = (nb == 3);

    #pragma unroll
    for (int mi = 0; mi < 4; mi++) {
        int row0 = bm + wm + mi * 16 + g;
        #pragma unroll
        for (int ni = 0; ni < 8; ni++) {
            int col = nc0 + wn + ni * 8 + cq * 2;
            float b0 = hasb ? bw[col]     : 0.f;
            float b1 = hasb ? bw[col + 1] : 0.f;
            float v0 = acc[mi][ni][0] + b0;
            float v1 = acc[mi][ni][1] + b1;
            float v2 = acc[mi][ni][2] + b0;
            float v3 = acc[mi][ni][3] + b1;
            if (sig) {
                v0 = 1.f / (1.f + expf(-v0));
                v1 = 1.f / (1.f + expf(-v1));
                v2 = 1.f / (1.f + expf(-v2));
                v3 = 1.f / (1.f + expf(-v3));
            }
            *(float2*)(dest + (size_t)row0 * D_M + col)       = make_float2(v0, v1);
            *(float2*)(dest + (size_t)(row0 + 8) * D_M + col) = make_float2(v2, v3);
        }
    }
}

// ---------------------------------------------------------------------------
// Pass A: per-chunk local scan. grid (BH_N, CH_N), 512 threads.
// ---------------------------------------------------------------------------
__global__ __launch_bounds__(512) void scan_chunk_kernel()
{
    __shared__ float sk[CH_L][64], sw[CH_L][64], sr[CH_L][64], sv[CH_L][64];

    int bh = blockIdx.x, ch = blockIdx.y;
    int b = bh >> 4, h = bh & 15;
    int tid = threadIdx.x;
    int e = tid >> 3, dq = tid & 7;

    size_t base = (size_t)b * T_N * D_M + (size_t)ch * CH_L * D_M + h * HS_N;

    {
        int t = tid >> 4, c = (tid & 15) * 4;
        size_t off = base + (size_t)t * D_M + c;
        cp16(&sk[t][c], g_k + off);
        cp16(&sw[t][c], g_w + off);
        cp16(&sr[t][c], g_r + off);
        cp16(&sv[t][c], g_v + off);
    }
    CP_COMMIT();
    cp_wait<0>();
    __syncthreads();

    float s[8], cum[8];
    #pragma unroll
    for (int i = 0; i < 8; i++) { s[i] = 0.f; cum[i] = 1.f; }

    float* op = g_o + base + e;
    float* qp = g_r + base + dq * 8;

    for (int t = 0; t < CH_L; t++) {
        float4 k0 = *(const float4*)&sk[t][dq * 8];
        float4 k1 = *(const float4*)&sk[t][dq * 8 + 4];
        float4 w0 = *(const float4*)&sw[t][dq * 8];
        float4 w1 = *(const float4*)&sw[t][dq * 8 + 4];
        float4 r0 = *(const float4*)&sr[t][dq * 8];
        float4 r1 = *(const float4*)&sr[t][dq * 8 + 4];
        float vv  = sv[t][e];

        float kc[8] = {k0.x, k0.y, k0.z, k0.w, k1.x, k1.y, k1.z, k1.w};
        float wc[8] = {w0.x, w0.y, w0.z, w0.w, w1.x, w1.y, w1.z, w1.w};
        float rc[8] = {r0.x, r0.y, r0.z, r0.w, r1.x, r1.y, r1.z, r1.w};

        float acc = 0.f;
        #pragma unroll
        for (int i = 0; i < 8; i++) {
            float omw = 1.f - wc[i];
            cum[i] *= omw;
            float si = fmaf(kc[i], vv, s[i] * omw);
            s[i] = si;
            acc = fmaf(rc[i], si, acc);
        }
        acc += __shfl_xor_sync(0xffffffffu, acc, 1);
        acc += __shfl_xor_sync(0xffffffffu, acc, 2);
        acc += __shfl_xor_sync(0xffffffffu, acc, 4);
        if (dq == 0) *op = acc;
        op += D_M;

        if (e == 0) {
            float q[8];
            #pragma unroll
            for (int i = 0; i < 8; i++) q[i] = rc[i] * cum[i];
            *(float4*)(qp)     = make_float4(q[0], q[1], q[2], q[3]);
            *(float4*)(qp + 4) = make_float4(q[4], q[5], q[6], q[7]);
        }
        qp += D_M;
    }

    size_t sb = ((size_t)bh * CH_N + ch) * (HS_N * HS_N) + (size_t)e * HS_N + dq * 8;
    *(float4*)(g_sloc + sb)     = make_float4(s[0], s[1], s[2], s[3]);
    *(float4*)(g_sloc + sb + 4) = make_float4(s[4], s[5], s[6], s[7]);

    if (e == 0) {
        size_t pb = ((size_t)bh * CH_N + ch) * HS_N + dq * 8;
        *(float4*)(g_pc + pb)     = make_float4(cum[0], cum[1], cum[2], cum[3]);
        *(float4*)(g_pc + pb + 4) = make_float4(cum[4], cum[5], cum[6], cum[7]);
    }
}

// ---------------------------------------------------------------------------
// Pass B: parallel chunk combine. grid (BH_N, 8), 512 threads.
// Thread = one (e, d): e = eg*8 + (tid>>6), d = tid&63. Scans 64 chunks.
// ---------------------------------------------------------------------------
__global__ __launch_bounds__(512) void combine_kernel(float* __restrict__ Sout)
{
    int bh = blockIdx.x;
    int eg = blockIdx.y;
    int tid = threadIdx.x;
    int e = eg * 8 + (tid >> 6);
    int d = tid & 63;

    size_t sbase = (size_t)bh * CH_N * (HS_N * HS_N) + (size_t)e * HS_N + d;
    size_t pbase = (size_t)bh * CH_N * HS_N + d;

    float carry = 0.f;
    #pragma unroll 4
    for (int ch = 0; ch < CH_N; ch++) {
        float pc = g_pc[pbase + (size_t)ch * HS_N];
        float sl = g_sloc[sbase + (size_t)ch * (HS_N * HS_N)];
        g_sin[sbase + (size_t)ch * (HS_N * HS_N)] = carry;
        carry = fmaf(pc, carry, sl);
    }

    // final state: Sout[bh][d][e]
    Sout[(size_t)bh * (HS_N * HS_N) + (size_t)d * HS_N + e] = carry;
}

// ---------------------------------------------------------------------------
// Pass C: out_t += q_t . s_in[ch]; round to tf32. grid (BH_N, CH_N), 256 thr.
// ---------------------------------------------------------------------------
__global__ __launch_bounds__(256) void corr_kernel()
{
    __shared__ float sq[CH_L][64];
    __shared__ float sS[64][68];

    int bh = blockIdx.x, ch = blockIdx.y;
    int b = bh >> 4, h = bh & 15;
    int tid = threadIdx.x;

    size_t qbase = (size_t)b * T_N * D_M + (size_t)ch * CH_L * D_M + h * HS_N;
    size_t sbase = ((size_t)bh * CH_N + ch) * (HS_N * HS_N);

    #pragma unroll
    for (int j = 0; j < 2; j++) {
        int f = tid + j * 256;
        int t = f >> 4, c = (f & 15) * 4;
        cp16(&sq[t][c], g_r + qbase + (size_t)t * D_M + c);
    }
    #pragma unroll
    for (int j = 0; j < 4; j++) {
        int f = tid + j * 256;
        int ee = f >> 4, d = (f & 15) * 4;
        cp16(&sS[ee][d], g_sin + sbase + (size_t)ee * HS_N + d);
    }
    CP_COMMIT();
    cp_wait<0>();
    __syncthreads();

    int tg = tid >> 5;
    int el = tid & 31;

    float a[4][2];
    #pragma unroll
    for (int j = 0; j < 4; j++) { a[j][0] = 0.f; a[j][1] = 0.f; }

    for (int d0 = 0; d0 < 64; d0 += 4) {
        float4 s0 = *(const float4*)&sS[el][d0];
        float4 s1 = *(const float4*)&sS[el + 32][d0];
        #pragma unroll
        for (int j = 0; j < 4; j++) {
            float4 qv = *(const float4*)&sq[tg * 4 + j][d0];
            a[j][0] = fmaf(qv.x, s0.x, fmaf(qv.y, s0.y, fmaf(qv.z, s0.z, fmaf(qv.w, s0.w, a[j][0]))));
            a[j][1] = fmaf(qv.x, s1.x, fmaf(qv.y, s1.y, fmaf(qv.z, s1.z, fmaf(qv.w, s1.w, a[j][1]))));
        }
    }

    #pragma unroll
    for (int j = 0; j < 4; j++) {
        float* p0 = g_o + qbase + (size_t)(tg * 4 + j) * D_M + el;
        float* p1 = p0 + 32;
        *p0 = to_tf32f(*p0 + a[j][0]);
        *p1 = to_tf32f(*p1 + a[j][1]);
    }
}

// ---------------------------------------------------------------------------
// Launch — kernel launches + func-attribute setup (graph-capture safe)
// ---------------------------------------------------------------------------
extern "C" void kernel_launch(void* const* d_in, const int* in_sizes, int n_in,
                              void* d_out, int out_size)
{
    const float* x    = (const float*)d_in[0];
    const float* ln_g = (const float*)d_in[1];
    const float* ln_b = (const float*)d_in[2];
    const float* Wx   = (const float*)d_in[3];
    const float* Ww   = (const float*)d_in[4];
    const float* bw   = (const float*)d_in[5];
    const float* Wk   = (const float*)d_in[6];
    const float* Wv   = (const float*)d_in[7];
    const float* Wr   = (const float*)d_in[8];
    const float* Wo   = (const float*)d_in[9];
    float* out = (float*)d_out;

    // Raise dynamic-smem cap for the 70KB GEMM kernels (immediate API, not
    // stream-ordered; legal under graph capture).
    cudaFuncSetAttribute(gemm_fused, cudaFuncAttributeMaxDynamicSharedMemorySize, GEMM_SMEM_BYTES);
    cudaFuncSetAttribute(gemm_wc,    cudaFuncAttributeMaxDynamicSharedMemorySize, GEMM_SMEM_BYTES);
    cudaFuncSetAttribute(gemm_tc<BUF_O, BUF_EXT, 6, 0, D_M, 0>,
                         cudaFuncAttributeMaxDynamicSharedMemorySize, GEMM_SMEM_BYTES);

    // 0) round + pack weights
    round_w_kernel<<<1024, 256>>>(Wx, Ww, Wk, Wv, Wr, Wo);

    // 0b) Wc = Wx_r @ Ww_r via split-K x4 (256 blocks) + reduce into slab 3
    gemm_wc<<<dim3(8, 8, 4), 128, GEMM_SMEM_BYTES>>>();
    wc_reduce<<<1024, 256>>>();

    // 1) LayerNorm -> g_xn (rounded)
    ln_kernel<<<MROWS, 256>>>(x, ln_g, ln_b);

    // 2) Fused projections: k, v, r=sig, w=sig(+bw)  (2048 blocks)
    gemm_fused<<<dim3(32, 64), 128, GEMM_SMEM_BYTES>>>(bw);

    // 3) Chunked parallel scan
    scan_chunk_kernel<<<dim3(BH_N, CH_N), 512>>>();
    combine_kernel<<<dim3(BH_N, 8), 512>>>(out + (size_t)MROWS * D_M);
    corr_kernel<<<dim3(BH_N, CH_N), 256>>>();

    // 4) y = o @ Wo -> head of d_out  (512 blocks)
    gemm_tc<BUF_O, BUF_EXT, 6, 0, D_M, 0><<<dim3(8, 64), 128, GEMM_SMEM_BYTES>>>(out);
}

// round 11
// speedup vs baseline: 1.4440x; 1.4440x over previous
#include <cuda_runtime.h>
#include <math.h>
#include <stdint.h>

// Problem constants
#define D_M   1024
#define B_N   4
#define T_N   2048
#define H_N   16
#define HS_N  64
#define MROWS (B_N * T_N)   // 8192
#define CH_L  32            // chunk length
#define CH_N  (T_N / CH_L)  // 64 chunks
#define BH_N  (B_N * H_N)   // 64

#define WM_SZ ((size_t)D_M * D_M)   // 1M floats

// ---------------------------------------------------------------------------
// Scratch (static device globals)
// ---------------------------------------------------------------------------
__device__ float g_xn[(size_t)MROWS * D_M];
__device__ float g_w [(size_t)MROWS * D_M];
__device__ float g_k [(size_t)MROWS * D_M];
__device__ float g_v [(size_t)MROWS * D_M];
__device__ float g_r [(size_t)MROWS * D_M];   // becomes q after pass A
__device__ float g_o [(size_t)MROWS * D_M];
// weight pool: [0..4M) packed [Wk|Wv|Wr|Wc] (row stride 4096)
//              [4M..5M) Wx_r  [5M..6M) Ww_r  [6M..7M) Wo_r (stride 1024)
__device__ float g_wt[(size_t)7 * WM_SZ];
__device__ float g_wcp[(size_t)4 * WM_SZ];                  // Wc split-K partials
__device__ float g_sloc[(size_t)BH_N * CH_N * HS_N * HS_N]; // [bh][ch][e][d]
__device__ float g_sin [(size_t)BH_N * CH_N * HS_N * HS_N]; // [bh][ch][e][d]
__device__ float g_pc  [(size_t)BH_N * CH_N * HS_N];        // [bh][ch][d]

enum Buf { BUF_XN = 0, BUF_O, BUF_EXT };

template <int B> __device__ __forceinline__ float* buf_ptr(float* ext) {
    if (B == BUF_XN) return g_xn;
    if (B == BUF_O)  return g_o;
    return ext;
}

// ---------------------------------------------------------------------------
// PTX helpers
// ---------------------------------------------------------------------------
__device__ __forceinline__ void cp16(void* smem_dst, const void* gsrc) {
    uint32_t s = (uint32_t)__cvta_generic_to_shared(smem_dst);
    asm volatile("cp.async.cg.shared.global [%0], [%1], 16;\n" :: "r"(s), "l"(gsrc));
}
#define CP_COMMIT() asm volatile("cp.async.commit_group;\n" ::: "memory")
template <int N> __device__ __forceinline__ void cp_wait() {
    asm volatile("cp.async.wait_group %0;\n" :: "n"(N) : "memory");
}
__device__ __forceinline__ float to_tf32f(float x) {
    uint32_t r;
    asm("cvt.rna.tf32.f32 %0, %1;\n" : "=r"(r) : "f"(x));
    return __uint_as_float(r);
}
__device__ __forceinline__ float4 rnd4(float4 v) {
    v.x = to_tf32f(v.x); v.y = to_tf32f(v.y);
    v.z = to_tf32f(v.z); v.w = to_tf32f(v.w);
    return v;
}
__device__ __forceinline__ void mma_tf32(float* c, const uint32_t* a, const uint32_t* b) {
    asm volatile(
        "mma.sync.aligned.m16n8k8.row.col.f32.tf32.tf32.f32 "
        "{%0,%1,%2,%3}, {%4,%5,%6,%7}, {%8,%9}, {%0,%1,%2,%3};\n"
        : "+f"(c[0]), "+f"(c[1]), "+f"(c[2]), "+f"(c[3])
        : "r"(a[0]), "r"(a[1]), "r"(a[2]), "r"(a[3]), "r"(b[0]), "r"(b[1]));
}

// ---------------------------------------------------------------------------
// round_w: tf32-round all weights. Wk,Wv,Wr -> packed slots 0..2;
// Wx -> +4M, Ww -> +5M, Wo -> +6M. grid 1024 x 256.
// ---------------------------------------------------------------------------
__global__ __launch_bounds__(256) void round_w_kernel(
    const float* __restrict__ Wx, const float* __restrict__ Ww,
    const float* __restrict__ Wk, const float* __restrict__ Wv,
    const float* __restrict__ Wr, const float* __restrict__ Wo)
{
    size_t idx = ((size_t)blockIdx.x * 256 + threadIdx.x) * 4;  // 0..1M step 4
    size_t k = idx >> 10, c = idx & 1023;

    *(float4*)(g_wt + k * 4096 + 0 * D_M + c) = rnd4(*(const float4*)(Wk + idx));
    *(float4*)(g_wt + k * 4096 + 1 * D_M + c) = rnd4(*(const float4*)(Wv + idx));
    *(float4*)(g_wt + k * 4096 + 2 * D_M + c) = rnd4(*(const float4*)(Wr + idx));
    *(float4*)(g_wt + 4 * WM_SZ + idx) = rnd4(*(const float4*)(Wx + idx));
    *(float4*)(g_wt + 5 * WM_SZ + idx) = rnd4(*(const float4*)(Ww + idx));
    *(float4*)(g_wt + 6 * WM_SZ + idx) = rnd4(*(const float4*)(Wo + idx));
}

// ---------------------------------------------------------------------------
// LayerNorm -> g_xn (tf32-rounded)
// ---------------------------------------------------------------------------
__global__ __launch_bounds__(256) void ln_kernel(
    const float* __restrict__ X, const float* __restrict__ G,
    const float* __restrict__ Bv)
{
    __shared__ float red[16];
    int row = blockIdx.x;
    int tid = threadIdx.x;
    const float* xr = X + (size_t)row * D_M;

    float4 xv = *(const float4*)(xr + tid * 4);
    float s = xv.x + xv.y + xv.z + xv.w;
    float q = xv.x * xv.x + xv.y * xv.y + xv.z * xv.z + xv.w * xv.w;

    #pragma unroll
    for (int o = 16; o > 0; o >>= 1) {
        s += __shfl_xor_sync(0xffffffffu, s, o);
        q += __shfl_xor_sync(0xffffffffu, q, o);
    }
    int wid = tid >> 5, lid = tid & 31;
    if (lid == 0) { red[wid] = s; red[8 + wid] = q; }
    __syncthreads();
    if (wid == 0) {
        float s2 = (lid < 8) ? red[lid] : 0.f;
        float q2 = (lid < 8) ? red[8 + lid] : 0.f;
        #pragma unroll
        for (int o = 4; o > 0; o >>= 1) {
            s2 += __shfl_xor_sync(0xffffffffu, s2, o);
            q2 += __shfl_xor_sync(0xffffffffu, q2, o);
        }
        if (lid == 0) { red[0] = s2; red[1] = q2; }
    }
    __syncthreads();

    float mu   = red[0] * (1.f / D_M);
    float var  = red[1] * (1.f / D_M) - mu * mu;
    float rstd = rsqrtf(var + 1e-5f);

    float4 gv = *(const float4*)(G + tid * 4);
    float4 bv = *(const float4*)(Bv + tid * 4);
    float4 yv;
    yv.x = to_tf32f((xv.x - mu) * rstd * gv.x + bv.x);
    yv.y = to_tf32f((xv.y - mu) * rstd * gv.y + bv.y);
    yv.z = to_tf32f((xv.z - mu) * rstd * gv.z + bv.z);
    yv.w = to_tf32f((xv.w - mu) * rstd * gv.w + bv.w);
    *(float4*)(g_xn + (size_t)row * D_M + tid * 4) = yv;
}

// ---------------------------------------------------------------------------
// GEMM core (round-8 proven config): one 128x128 tile over K range
// [kbeg, kend). BK=16, 2-stage cp.async, 4 warps, warp tile 64x64.
// Static smem As[2][128][20], Bs[2][16][136].
// ---------------------------------------------------------------------------
template <int WS>
__device__ __forceinline__ void gemm_tile(
    const float* __restrict__ A, const float* __restrict__ Wm,
    int bm, int bn, int tid, float acc[4][8][4],
    float As[2][128][20], float Bs[2][16][136],
    int kbeg, int kend)
{
    auto load_stage = [&](int buf, int k0) {
        #pragma unroll
        for (int j = 0; j < 4; j++) {
            int f   = tid + j * 128;
            int row = f >> 2;
            int kc  = (f & 3) << 2;
            cp16(&As[buf][row][kc], A + (size_t)(bm + row) * D_M + k0 + kc);
        }
        #pragma unroll
        for (int j = 0; j < 4; j++) {
            int f  = tid + j * 128;
            int kr = f >> 5;
            int nc = (f & 31) << 2;
            cp16(&Bs[buf][kr][nc], Wm + (size_t)(k0 + kr) * WS + bn + nc);
        }
        CP_COMMIT();
    };

    int wid = tid >> 5, lane = tid & 31;
    int g = lane >> 2, cq = lane & 3;
    int wm = (wid & 1) * 64, wn = (wid >> 1) * 64;
    int nkt = (kend - kbeg) >> 4;

    load_stage(0, kbeg);

    for (int kt = 0; kt < nkt; kt++) {
        int buf = kt & 1;
        if (kt < nkt - 1) {
            load_stage(buf ^ 1, kbeg + (kt + 1) * 16);
            cp_wait<1>();
        } else {
            cp_wait<0>();
        }
        __syncthreads();

        #pragma unroll
        for (int ks = 0; ks < 2; ks++) {
            uint32_t af[4][4], bf[8][2];
            #pragma unroll
            for (int mi = 0; mi < 4; mi++) {
                int r0 = wm + mi * 16 + g;
                af[mi][0] = *(const uint32_t*)&As[buf][r0    ][ks * 8 + cq];
                af[mi][1] = *(const uint32_t*)&As[buf][r0 + 8][ks * 8 + cq];
                af[mi][2] = *(const uint32_t*)&As[buf][r0    ][ks * 8 + cq + 4];
                af[mi][3] = *(const uint32_t*)&As[buf][r0 + 8][ks * 8 + cq + 4];
            }
            #pragma unroll
            for (int ni = 0; ni < 8; ni++) {
                int c0 = wn + ni * 8 + g;
                bf[ni][0] = *(const uint32_t*)&Bs[buf][ks * 8 + cq    ][c0];
                bf[ni][1] = *(const uint32_t*)&Bs[buf][ks * 8 + cq + 4][c0];
            }
            #pragma unroll
            for (int mi = 0; mi < 4; mi++)
                #pragma unroll
                for (int ni = 0; ni < 8; ni++)
                    mma_tf32(acc[mi][ni], af[mi], bf[ni]);
        }
        __syncthreads();
    }
}

#define ACC_INIT(acc) \
    _Pragma("unroll") \
    for (int mi = 0; mi < 4; mi++) \
        _Pragma("unroll") \
        for (int ni = 0; ni < 8; ni++) \
            _Pragma("unroll") \
            for (int x = 0; x < 4; x++) acc[mi][ni][x] = 0.f

// ---------------------------------------------------------------------------
// Generic GEMM: C = act(A @ W); W at g_wt+WOFF*1M (stride 1024),
// C row stride CS. FLAGS: bit0 sigmoid, bit2 round.
// ---------------------------------------------------------------------------
template <int ASEL, int CSEL, int WOFF, int COFF, int CS, int FLAGS>
__global__ __launch_bounds__(128) void gemm_tc(float* __restrict__ Cext)
{
    __shared__ float As[2][128][20];
    __shared__ float Bs[2][16][136];

    const float* A  = buf_ptr<ASEL>(nullptr);
    const float* Wm = g_wt + (size_t)WOFF * WM_SZ;
    float*       C  = buf_ptr<CSEL>(Cext) + COFF;

    int tid = threadIdx.x;
    int bm = blockIdx.y * 128, bn = blockIdx.x * 128;

    float acc[4][8][4];
    ACC_INIT(acc);

    gemm_tile<D_M>(A, Wm, bm, bn, tid, acc, As, Bs, 0, D_M);

    int wid = tid >> 5, lane = tid & 31;
    int g = lane >> 2, cq = lane & 3;
    int wm = (wid & 1) * 64, wn = (wid >> 1) * 64;

    #pragma unroll
    for (int mi = 0; mi < 4; mi++) {
        int row0 = bm + wm + mi * 16 + g;
        #pragma unroll
        for (int ni = 0; ni < 8; ni++) {
            int col = bn + wn + ni * 8 + cq * 2;
            float v0 = acc[mi][ni][0];
            float v1 = acc[mi][ni][1];
            float v2 = acc[mi][ni][2];
            float v3 = acc[mi][ni][3];
            if (FLAGS & 1) {
                v0 = 1.f / (1.f + expf(-v0));
                v1 = 1.f / (1.f + expf(-v1));
                v2 = 1.f / (1.f + expf(-v2));
                v3 = 1.f / (1.f + expf(-v3));
            }
            if (FLAGS & 4) {
                v0 = to_tf32f(v0); v1 = to_tf32f(v1);
                v2 = to_tf32f(v2); v3 = to_tf32f(v3);
            }
            *(float2*)(C + (size_t)row0 * CS + col)       = make_float2(v0, v1);
            *(float2*)(C + (size_t)(row0 + 8) * CS + col) = make_float2(v2, v3);
        }
    }
}

// ---------------------------------------------------------------------------
// Wc split-K partial: g_wcp[z] = Wx_r @ Ww_r over K slice z*256..+256.
// grid (8, 8, 4). BK=16 core.
// ---------------------------------------------------------------------------
__global__ __launch_bounds__(128) void gemm_wc(void)
{
    __shared__ float As[2][128][20];
    __shared__ float Bs[2][16][136];

    const float* A  = g_wt + 4 * WM_SZ;   // Wx_r
    const float* Wm = g_wt + 5 * WM_SZ;   // Ww_r
    float*       C  = g_wcp + (size_t)blockIdx.z * WM_SZ;

    int tid = threadIdx.x;
    int bm = blockIdx.y * 128, bn = blockIdx.x * 128;
    int kbeg = blockIdx.z * 256;

    float acc[4][8][4];
    ACC_INIT(acc);

    gemm_tile<D_M>(A, Wm, bm, bn, tid, acc, As, Bs, kbeg, kbeg + 256);

    int wid = tid >> 5, lane = tid & 31;
    int g = lane >> 2, cq = lane & 3;
    int wm = (wid & 1) * 64, wn = (wid >> 1) * 64;

    #pragma unroll
    for (int mi = 0; mi < 4; mi++) {
        int row0 = bm + wm + mi * 16 + g;
        #pragma unroll
        for (int ni = 0; ni < 8; ni++) {
            int col = bn + wn + ni * 8 + cq * 2;
            *(float2*)(C + (size_t)row0 * D_M + col)       = make_float2(acc[mi][ni][0], acc[mi][ni][1]);
            *(float2*)(C + (size_t)(row0 + 8) * D_M + col) = make_float2(acc[mi][ni][2], acc[mi][ni][3]);
        }
    }
}

// ---------------------------------------------------------------------------
// Wc reduce: sum 4 partials, round, write packed slab 3. grid 1024 x 256.
// ---------------------------------------------------------------------------
__global__ __launch_bounds__(256) void wc_reduce(void)
{
    size_t idx = ((size_t)blockIdx.x * 256 + threadIdx.x) * 4;
    size_t k = idx >> 10, c = idx & 1023;

    float4 a = *(const float4*)(g_wcp + idx);
    float4 b = *(const float4*)(g_wcp + WM_SZ + idx);
    float4 d = *(const float4*)(g_wcp + 2 * WM_SZ + idx);
    float4 e = *(const float4*)(g_wcp + 3 * WM_SZ + idx);
    float4 s;
    s.x = a.x + b.x + d.x + e.x;
    s.y = a.y + b.y + d.y + e.y;
    s.z = a.z + b.z + d.z + e.z;
    s.w = a.w + b.w + d.w + e.w;
    *(float4*)(g_wt + k * 4096 + 3 * D_M + c) = rnd4(s);
}

// ---------------------------------------------------------------------------
// Fused projection GEMM: xn[8192][1024] @ packed[1024][4096].
// n-slab 0 -> g_k, 1 -> g_v, 2 -> sigmoid -> g_r, 3 -> sigmoid(+bw) -> g_w.
// grid (32, 64).
// ---------------------------------------------------------------------------
__global__ __launch_bounds__(128) void gemm_fused(const float* __restrict__ bw)
{
    __shared__ float As[2][128][20];
    __shared__ float Bs[2][16][136];

    int tid = threadIdx.x;
    int bm = blockIdx.y * 128, bn = blockIdx.x * 128;

    float acc[4][8][4];
    ACC_INIT(acc);

    gemm_tile<4096>(g_xn, g_wt, bm, bn, tid, acc, As, Bs, 0, D_M);

    int wid = tid >> 5, lane = tid & 31;
    int g = lane >> 2, cq = lane & 3;
    int wm = (wid & 1) * 64, wn = (wid >> 1) * 64;

    int nb = bn >> 10;          // slab
    int nc0 = bn & 1023;        // local col base
    float* dest = (nb == 0) ? g_k : (nb == 1) ? g_v : (nb == 2) ? g_r : g_w;
    bool sig = (nb >= 2);
    bool hasb = (nb == 3);

    #pragma unroll
    for (int mi = 0; mi < 4; mi++) {
        int row0 = bm + wm + mi * 16 + g;
        #pragma unroll
        for (int ni = 0; ni < 8; ni++) {
            int col = nc0 + wn + ni * 8 + cq * 2;
            float b0 = hasb ? bw[col]     : 0.f;
            float b1 = hasb ? bw[col + 1] : 0.f;
            float v0 = acc[mi][ni][0] + b0;
            float v1 = acc[mi][ni][1] + b1;
            float v2 = acc[mi][ni][2] + b0;
            float v3 = acc[mi][ni][3] + b1;
            if (sig) {
                v0 = 1.f / (1.f + expf(-v0));
                v1 = 1.f / (1.f + expf(-v1));
                v2 = 1.f / (1.f + expf(-v2));
                v3 = 1.f / (1.f + expf(-v3));
            }
            *(float2*)(dest + (size_t)row0 * D_M + col)       = make_float2(v0, v1);
            *(float2*)(dest + (size_t)(row0 + 8) * D_M + col) = make_float2(v2, v3);
        }
    }
}

// ---------------------------------------------------------------------------
// Pass A: per-chunk local scan. grid (BH_N, CH_N), 512 threads.
// ---------------------------------------------------------------------------
__global__ __launch_bounds__(512) void scan_chunk_kernel()
{
    __shared__ float sk[CH_L][64], sw[CH_L][64], sr[CH_L][64], sv[CH_L][64];

    int bh = blockIdx.x, ch = blockIdx.y;
    int b = bh >> 4, h = bh & 15;
    int tid = threadIdx.x;
    int e = tid >> 3, dq = tid & 7;

    size_t base = (size_t)b * T_N * D_M + (size_t)ch * CH_L * D_M + h * HS_N;

    {
        int t = tid >> 4, c = (tid & 15) * 4;
        size_t off = base + (size_t)t * D_M + c;
        cp16(&sk[t][c], g_k + off);
        cp16(&sw[t][c], g_w + off);
        cp16(&sr[t][c], g_r + off);
        cp16(&sv[t][c], g_v + off);
    }
    CP_COMMIT();
    cp_wait<0>();
    __syncthreads();

    float s[8], cum[8];
    #pragma unroll
    for (int i = 0; i < 8; i++) { s[i] = 0.f; cum[i] = 1.f; }

    float* op = g_o + base + e;
    float* qp = g_r + base + dq * 8;

    for (int t = 0; t < CH_L; t++) {
        float4 k0 = *(const float4*)&sk[t][dq * 8];
        float4 k1 = *(const float4*)&sk[t][dq * 8 + 4];
        float4 w0 = *(const float4*)&sw[t][dq * 8];
        float4 w1 = *(const float4*)&sw[t][dq * 8 + 4];
        float4 r0 = *(const float4*)&sr[t][dq * 8];
        float4 r1 = *(const float4*)&sr[t][dq * 8 + 4];
        float vv  = sv[t][e];

        float kc[8] = {k0.x, k0.y, k0.z, k0.w, k1.x, k1.y, k1.z, k1.w};
        float wc[8] = {w0.x, w0.y, w0.z, w0.w, w1.x, w1.y, w1.z, w1.w};
        float rc[8] = {r0.x, r0.y, r0.z, r0.w, r1.x, r1.y, r1.z, r1.w};

        float acc = 0.f;
        #pragma unroll
        for (int i = 0; i < 8; i++) {
            float omw = 1.f - wc[i];
            cum[i] *= omw;
            float si = fmaf(kc[i], vv, s[i] * omw);
            s[i] = si;
            acc = fmaf(rc[i], si, acc);
        }
        acc += __shfl_xor_sync(0xffffffffu, acc, 1);
        acc += __shfl_xor_sync(0xffffffffu, acc, 2);
        acc += __shfl_xor_sync(0xffffffffu, acc, 4);
        if (dq == 0) *op = acc;
        op += D_M;

        if (e == 0) {
            float q[8];
            #pragma unroll
            for (int i = 0; i < 8; i++) q[i] = rc[i] * cum[i];
            *(float4*)(qp)     = make_float4(q[0], q[1], q[2], q[3]);
            *(float4*)(qp + 4) = make_float4(q[4], q[5], q[6], q[7]);
        }
        qp += D_M;
    }

    size_t sb = ((size_t)bh * CH_N + ch) * (HS_N * HS_N) + (size_t)e * HS_N + dq * 8;
    *(float4*)(g_sloc + sb)     = make_float4(s[0], s[1], s[2], s[3]);
    *(float4*)(g_sloc + sb + 4) = make_float4(s[4], s[5], s[6], s[7]);

    if (e == 0) {
        size_t pb = ((size_t)bh * CH_N + ch) * HS_N + dq * 8;
        *(float4*)(g_pc + pb)     = make_float4(cum[0], cum[1], cum[2], cum[3]);
        *(float4*)(g_pc + pb + 4) = make_float4(cum[4], cum[5], cum[6], cum[7]);
    }
}

// ---------------------------------------------------------------------------
// Pass B: parallel chunk combine. grid (BH_N, 8), 512 threads.
// Thread = one (e, d): e = eg*8 + (tid>>6), d = tid&63. Scans 64 chunks.
// ---------------------------------------------------------------------------
__global__ __launch_bounds__(512) void combine_kernel(float* __restrict__ Sout)
{
    int bh = blockIdx.x;
    int eg = blockIdx.y;
    int tid = threadIdx.x;
    int e = eg * 8 + (tid >> 6);
    int d = tid & 63;

    size_t sbase = (size_t)bh * CH_N * (HS_N * HS_N) + (size_t)e * HS_N + d;
    size_t pbase = (size_t)bh * CH_N * HS_N + d;

    float carry = 0.f;
    #pragma unroll 4
    for (int ch = 0; ch < CH_N; ch++) {
        float pc = g_pc[pbase + (size_t)ch * HS_N];
        float sl = g_sloc[sbase + (size_t)ch * (HS_N * HS_N)];
        g_sin[sbase + (size_t)ch * (HS_N * HS_N)] = carry;
        carry = fmaf(pc, carry, sl);
    }

    // final state: Sout[bh][d][e]
    Sout[(size_t)bh * (HS_N * HS_N) + (size_t)d * HS_N + e] = carry;
}

// ---------------------------------------------------------------------------
// Pass C: out_t += q_t . s_in[ch]; round to tf32. grid (BH_N, CH_N), 256 thr.
// ---------------------------------------------------------------------------
__global__ __launch_bounds__(256) void corr_kernel()
{
    __shared__ float sq[CH_L][64];
    __shared__ float sS[64][68];

    int bh = blockIdx.x, ch = blockIdx.y;
    int b = bh >> 4, h = bh & 15;
    int tid = threadIdx.x;

    size_t qbase = (size_t)b * T_N * D_M + (size_t)ch * CH_L * D_M + h * HS_N;
    size_t sbase = ((size_t)bh * CH_N + ch) * (HS_N * HS_N);

    #pragma unroll
    for (int j = 0; j < 2; j++) {
        int f = tid + j * 256;
        int t = f >> 4, c = (f & 15) * 4;
        cp16(&sq[t][c], g_r + qbase + (size_t)t * D_M + c);
    }
    #pragma unroll
    for (int j = 0; j < 4; j++) {
        int f = tid + j * 256;
        int ee = f >> 4, d = (f & 15) * 4;
        cp16(&sS[ee][d], g_sin + sbase + (size_t)ee * HS_N + d);
    }
    CP_COMMIT();
    cp_wait<0>();
    __syncthreads();

    int tg = tid >> 5;
    int el = tid & 31;

    float a[4][2];
    #pragma unroll
    for (int j = 0; j < 4; j++) { a[j][0] = 0.f; a[j][1] = 0.f; }

    for (int d0 = 0; d0 < 64; d0 += 4) {
        float4 s0 = *(const float4*)&sS[el][d0];
        float4 s1 = *(const float4*)&sS[el + 32][d0];
        #pragma unroll
        for (int j = 0; j < 4; j++) {
            float4 qv = *(const float4*)&sq[tg * 4 + j][d0];
            a[j][0] = fmaf(qv.x, s0.x, fmaf(qv.y, s0.y, fmaf(qv.z, s0.z, fmaf(qv.w, s0.w, a[j][0]))));
            a[j][1] = fmaf(qv.x, s1.x, fmaf(qv.y, s1.y, fmaf(qv.z, s1.z, fmaf(qv.w, s1.w, a[j][1]))));
        }
    }

    #pragma unroll
    for (int j = 0; j < 4; j++) {
        float* p0 = g_o + qbase + (size_t)(tg * 4 + j) * D_M + el;
        float* p1 = p0 + 32;
        *p0 = to_tf32f(*p0 + a[j][0]);
        *p1 = to_tf32f(*p1 + a[j][1]);
    }
}

// ---------------------------------------------------------------------------
// Launch — kernel launches ONLY (graph-capture safe)
// ---------------------------------------------------------------------------
extern "C" void kernel_launch(void* const* d_in, const int* in_sizes, int n_in,
                              void* d_out, int out_size)
{
    const float* x    = (const float*)d_in[0];
    const float* ln_g = (const float*)d_in[1];
    const float* ln_b = (const float*)d_in[2];
    const float* Wx   = (const float*)d_in[3];
    const float* Ww   = (const float*)d_in[4];
    const float* bw   = (const float*)d_in[5];
    const float* Wk   = (const float*)d_in[6];
    const float* Wv   = (const float*)d_in[7];
    const float* Wr   = (const float*)d_in[8];
    const float* Wo   = (const float*)d_in[9];
    float* out = (float*)d_out;

    // 0) round + pack weights
    round_w_kernel<<<1024, 256>>>(Wx, Ww, Wk, Wv, Wr, Wo);

    // 0b) Wc = Wx_r @ Ww_r via split-K x4 (256 blocks) + reduce into slab 3
    gemm_wc<<<dim3(8, 8, 4), 128>>>();
    wc_reduce<<<1024, 256>>>();

    // 1) LayerNorm -> g_xn (rounded)
    ln_kernel<<<MROWS, 256>>>(x, ln_g, ln_b);

    // 2) Fused projections: k, v, r=sig, w=sig(+bw)  (2048 blocks)
    gemm_fused<<<dim3(32, 64), 128>>>(bw);

    // 3) Chunked parallel scan
    scan_chunk_kernel<<<dim3(BH_N, CH_N), 512>>>();
    combine_kernel<<<dim3(BH_N, 8), 512>>>(out + (size_t)MROWS * D_M);
    corr_kernel<<<dim3(BH_N, CH_N), 256>>>();

    // 4) y = o @ Wo -> head of d_out  (512 blocks)
    gemm_tc<BUF_O, BUF_EXT, 6, 0, D_M, 0><<<dim3(8, 64), 128>>>(out);
}

// round 17
// speedup vs baseline: 1.4614x; 1.0120x over previous
#include <cuda_runtime.h>
#include <math.h>
#include <stdint.h>

// Problem constants
#define D_M   1024
#define B_N   4
#define T_N   2048
#define H_N   16
#define HS_N  64
#define MROWS (B_N * T_N)   // 8192
#define CH_L  32            // chunk length
#define CH_N  (T_N / CH_L)  // 64 chunks
#define BH_N  (B_N * H_N)   // 64

#define WM_SZ ((size_t)D_M * D_M)   // 1M floats

// ---------------------------------------------------------------------------
// Scratch (static device globals)
// ---------------------------------------------------------------------------
__device__ float g_xn[(size_t)MROWS * D_M];
__device__ float g_w [(size_t)MROWS * D_M];
__device__ float g_k [(size_t)MROWS * D_M];
__device__ float g_v [(size_t)MROWS * D_M];
__device__ float g_r [(size_t)MROWS * D_M];   // becomes q after pass A
__device__ float g_o [(size_t)MROWS * D_M];
// weight pool: [0..4M) packed [Wk|Wv|Wr|Wc] (row stride 4096)
//              [4M..5M) Wx_r  [5M..6M) Ww_r  [6M..7M) Wo_r (stride 1024)
__device__ float g_wt[(size_t)7 * WM_SZ];
__device__ float g_wcp[(size_t)4 * WM_SZ];                  // Wc split-K partials
__device__ float g_sloc[(size_t)BH_N * CH_N * HS_N * HS_N]; // [bh][ch][e][d]
__device__ float g_sin [(size_t)BH_N * CH_N * HS_N * HS_N]; // [bh][ch][e][d]
__device__ float g_pc  [(size_t)BH_N * CH_N * HS_N];        // [bh][ch][d]

// ---------------------------------------------------------------------------
// PTX helpers
// ---------------------------------------------------------------------------
__device__ __forceinline__ void cp16(void* smem_dst, const void* gsrc) {
    uint32_t s = (uint32_t)__cvta_generic_to_shared(smem_dst);
    asm volatile("cp.async.cg.shared.global [%0], [%1], 16;\n" :: "r"(s), "l"(gsrc));
}
#define CP_COMMIT() asm volatile("cp.async.commit_group;\n" ::: "memory")
template <int N> __device__ __forceinline__ void cp_wait() {
    asm volatile("cp.async.wait_group %0;\n" :: "n"(N) : "memory");
}
__device__ __forceinline__ float to_tf32f(float x) {
    uint32_t r;
    asm("cvt.rna.tf32.f32 %0, %1;\n" : "=r"(r) : "f"(x));
    return __uint_as_float(r);
}
__device__ __forceinline__ float4 rnd4(float4 v) {
    v.x = to_tf32f(v.x); v.y = to_tf32f(v.y);
    v.z = to_tf32f(v.z); v.w = to_tf32f(v.w);
    return v;
}
__device__ __forceinline__ void mma_tf32(float* c, const uint32_t* a, const uint32_t* b) {
    asm volatile(
        "mma.sync.aligned.m16n8k8.row.col.f32.tf32.tf32.f32 "
        "{%0,%1,%2,%3}, {%4,%5,%6,%7}, {%8,%9}, {%0,%1,%2,%3};\n"
        : "+f"(c[0]), "+f"(c[1]), "+f"(c[2]), "+f"(c[3])
        : "r"(a[0]), "r"(a[1]), "r"(a[2]), "r"(a[3]), "r"(b[0]), "r"(b[1]));
}

// ---------------------------------------------------------------------------
// round_w: tf32-round all weights. Wk,Wv,Wr -> packed slots 0..2;
// Wx -> +4M, Ww -> +5M, Wo -> +6M. grid 1024 x 256.
// ---------------------------------------------------------------------------
__global__ __launch_bounds__(256) void round_w_kernel(
    const float* __restrict__ Wx, const float* __restrict__ Ww,
    const float* __restrict__ Wk, const float* __restrict__ Wv,
    const float* __restrict__ Wr, const float* __restrict__ Wo)
{
    size_t idx = ((size_t)blockIdx.x * 256 + threadIdx.x) * 4;  // 0..1M step 4
    size_t k = idx >> 10, c = idx & 1023;

    *(float4*)(g_wt + k * 4096 + 0 * D_M + c) = rnd4(*(const float4*)(Wk + idx));
    *(float4*)(g_wt + k * 4096 + 1 * D_M + c) = rnd4(*(const float4*)(Wv + idx));
    *(float4*)(g_wt + k * 4096 + 2 * D_M + c) = rnd4(*(const float4*)(Wr + idx));
    *(float4*)(g_wt + 4 * WM_SZ + idx) = rnd4(*(const float4*)(Wx + idx));
    *(float4*)(g_wt + 5 * WM_SZ + idx) = rnd4(*(const float4*)(Ww + idx));
    *(float4*)(g_wt + 6 * WM_SZ + idx) = rnd4(*(const float4*)(Wo + idx));
}

// ---------------------------------------------------------------------------
// LayerNorm -> g_xn (tf32-rounded)
// ---------------------------------------------------------------------------
__global__ __launch_bounds__(256) void ln_kernel(
    const float* __restrict__ X, const float* __restrict__ G,
    const float* __restrict__ Bv)
{
    __shared__ float red[16];
    int row = blockIdx.x;
    int tid = threadIdx.x;
    const float* xr = X + (size_t)row * D_M;

    float4 xv = *(const float4*)(xr + tid * 4);
    float s = xv.x + xv.y + xv.z + xv.w;
    float q = xv.x * xv.x + xv.y * xv.y + xv.z * xv.z + xv.w * xv.w;

    #pragma unroll
    for (int o = 16; o > 0; o >>= 1) {
        s += __shfl_xor_sync(0xffffffffu, s, o);
        q += __shfl_xor_sync(0xffffffffu, q, o);
    }
    int wid = tid >> 5, lid = tid & 31;
    if (lid == 0) { red[wid] = s; red[8 + wid] = q; }
    __syncthreads();
    if (wid == 0) {
        float s2 = (lid < 8) ? red[lid] : 0.f;
        float q2 = (lid < 8) ? red[8 + lid] : 0.f;
        #pragma unroll
        for (int o = 4; o > 0; o >>= 1) {
            s2 += __shfl_xor_sync(0xffffffffu, s2, o);
            q2 += __shfl_xor_sync(0xffffffffu, q2, o);
        }
        if (lid == 0) { red[0] = s2; red[1] = q2; }
    }
    __syncthreads();

    float mu   = red[0] * (1.f / D_M);
    float var  = red[1] * (1.f / D_M) - mu * mu;
    float rstd = rsqrtf(var + 1e-5f);

    float4 gv = *(const float4*)(G + tid * 4);
    float4 bv = *(const float4*)(Bv + tid * 4);
    float4 yv;
    yv.x = to_tf32f((xv.x - mu) * rstd * gv.x + bv.x);
    yv.y = to_tf32f((xv.y - mu) * rstd * gv.y + bv.y);
    yv.z = to_tf32f((xv.z - mu) * rstd * gv.z + bv.z);
    yv.w = to_tf32f((xv.w - mu) * rstd * gv.w + bv.w);
    *(float4*)(g_xn + (size_t)row * D_M + tid * 4) = yv;
}

// ---------------------------------------------------------------------------
// 256-thread GEMM core: 128x128 tile, BK=16, 2-stage cp.async,
// 8 warps, warp tile 64x32 (acc[4][4][4] = 64 regs). 2 CTAs/SM target.
// ---------------------------------------------------------------------------
template <int WS>
__device__ __forceinline__ void gemm_tile256(
    const float* __restrict__ A, const float* __restrict__ Wm,
    int bm, int bn, int tid, float acc[4][4][4],
    float As[2][128][20], float Bs[2][16][136])
{
    auto load_stage = [&](int buf, int k0) {
        #pragma unroll
        for (int j = 0; j < 2; j++) {
            int f   = tid + j * 256;          // 0..511
            int row = f >> 2;
            int kc  = (f & 3) << 2;
            cp16(&As[buf][row][kc], A + (size_t)(bm + row) * D_M + k0 + kc);
        }
        #pragma unroll
        for (int j = 0; j < 2; j++) {
            int f  = tid + j * 256;
            int kr = f >> 5;
            int nc = (f & 31) << 2;
            cp16(&Bs[buf][kr][nc], Wm + (size_t)(k0 + kr) * WS + bn + nc);
        }
        CP_COMMIT();
    };

    int wid = tid >> 5, lane = tid & 31;
    int g = lane >> 2, cq = lane & 3;
    int wm = (wid & 1) * 64, wn = (wid >> 1) * 32;

    load_stage(0, 0);

    for (int kt = 0; kt < D_M / 16; kt++) {
        int buf = kt & 1;
        if (kt < D_M / 16 - 1) {
            load_stage(buf ^ 1, (kt + 1) * 16);
            cp_wait<1>();
        } else {
            cp_wait<0>();
        }
        __syncthreads();

        #pragma unroll
        for (int ks = 0; ks < 2; ks++) {
            uint32_t af[4][4], bf[4][2];
            #pragma unroll
            for (int mi = 0; mi < 4; mi++) {
                int r0 = wm + mi * 16 + g;
                af[mi][0] = *(const uint32_t*)&As[buf][r0    ][ks * 8 + cq];
                af[mi][1] = *(const uint32_t*)&As[buf][r0 + 8][ks * 8 + cq];
                af[mi][2] = *(const uint32_t*)&As[buf][r0    ][ks * 8 + cq + 4];
                af[mi][3] = *(const uint32_t*)&As[buf][r0 + 8][ks * 8 + cq + 4];
            }
            #pragma unroll
            for (int ni = 0; ni < 4; ni++) {
                int c0 = wn + ni * 8 + g;
                bf[ni][0] = *(const uint32_t*)&Bs[buf][ks * 8 + cq    ][c0];
                bf[ni][1] = *(const uint32_t*)&Bs[buf][ks * 8 + cq + 4][c0];
            }
            #pragma unroll
            for (int mi = 0; mi < 4; mi++)
                #pragma unroll
                for (int ni = 0; ni < 4; ni++)
                    mma_tf32(acc[mi][ni], af[mi], bf[ni]);
        }
        __syncthreads();
    }
}

#define ACC_INIT44(acc) \
    _Pragma("unroll") \
    for (int mi = 0; mi < 4; mi++) \
        _Pragma("unroll") \
        for (int ni = 0; ni < 4; ni++) \
            _Pragma("unroll") \
            for (int x = 0; x < 4; x++) acc[mi][ni][x] = 0.f

// ---------------------------------------------------------------------------
// Wo GEMM (256-thread core): out = g_o @ Wo_r. grid (8, 64).
// ---------------------------------------------------------------------------
__global__ __launch_bounds__(256, 2) void gemm_out(float* __restrict__ C)
{
    __shared__ float As[2][128][20];
    __shared__ float Bs[2][16][136];

    const float* Wm = g_wt + (size_t)6 * WM_SZ;

    int tid = threadIdx.x;
    int bm = blockIdx.y * 128, bn = blockIdx.x * 128;

    float acc[4][4][4];
    ACC_INIT44(acc);

    gemm_tile256<D_M>(g_o, Wm, bm, bn, tid, acc, As, Bs);

    int wid = tid >> 5, lane = tid & 31;
    int g = lane >> 2, cq = lane & 3;
    int wm = (wid & 1) * 64, wn = (wid >> 1) * 32;

    #pragma unroll
    for (int mi = 0; mi < 4; mi++) {
        int row0 = bm + wm + mi * 16 + g;
        #pragma unroll
        for (int ni = 0; ni < 4; ni++) {
            int col = bn + wn + ni * 8 + cq * 2;
            *(float2*)(C + (size_t)row0 * D_M + col)       = make_float2(acc[mi][ni][0], acc[mi][ni][1]);
            *(float2*)(C + (size_t)(row0 + 8) * D_M + col) = make_float2(acc[mi][ni][2], acc[mi][ni][3]);
        }
    }
}

// ---------------------------------------------------------------------------
// Fused projection GEMM (256-thread core): xn @ packed[1024][4096].
// n-slab 0 -> g_k, 1 -> g_v, 2 -> sigmoid -> g_r, 3 -> sigmoid(+bw) -> g_w.
// grid (32, 64).
// ---------------------------------------------------------------------------
__global__ __launch_bounds__(256, 2) void gemm_fused(const float* __restrict__ bw)
{
    __shared__ float As[2][128][20];
    __shared__ float Bs[2][16][136];

    int tid = threadIdx.x;
    int bm = blockIdx.y * 128, bn = blockIdx.x * 128;

    float acc[4][4][4];
    ACC_INIT44(acc);

    gemm_tile256<4096>(g_xn, g_wt, bm, bn, tid, acc, As, Bs);

    int wid = tid >> 5, lane = tid & 31;
    int g = lane >> 2, cq = lane & 3;
    int wm = (wid & 1) * 64, wn = (wid >> 1) * 32;

    int nb = bn >> 10;          // slab
    int nc0 = bn & 1023;        // local col base
    float* dest = (nb == 0) ? g_k : (nb == 1) ? g_v : (nb == 2) ? g_r : g_w;
    bool sig = (nb >= 2);
    bool hasb = (nb == 3);

    #pragma unroll
    for (int mi = 0; mi < 4; mi++) {
        int row0 = bm + wm + mi * 16 + g;
        #pragma unroll
        for (int ni = 0; ni < 4; ni++) {
            int col = nc0 + wn + ni * 8 + cq * 2;
            float b0 = hasb ? bw[col]     : 0.f;
            float b1 = hasb ? bw[col + 1] : 0.f;
            float v0 = acc[mi][ni][0] + b0;
            float v1 = acc[mi][ni][1] + b1;
            float v2 = acc[mi][ni][2] + b0;
            float v3 = acc[mi][ni][3] + b1;
            if (sig) {
                v0 = 1.f / (1.f + expf(-v0));
                v1 = 1.f / (1.f + expf(-v1));
                v2 = 1.f / (1.f + expf(-v2));
                v3 = 1.f / (1.f + expf(-v3));
            }
            *(float2*)(dest + (size_t)row0 * D_M + col)       = make_float2(v0, v1);
            *(float2*)(dest + (size_t)(row0 + 8) * D_M + col) = make_float2(v2, v3);
        }
    }
}

// ---------------------------------------------------------------------------
// 128-thread GEMM core (proven; used by Wc only). BK=16, warp 64x64.
// ---------------------------------------------------------------------------
__device__ __forceinline__ void gemm_tile128(
    const float* __restrict__ A, const float* __restrict__ Wm,
    int bm, int bn, int tid, float acc[4][8][4],
    float As[2][128][20], float Bs[2][16][136],
    int kbeg, int kend)
{
    auto load_stage = [&](int buf, int k0) {
        #pragma unroll
        for (int j = 0; j < 4; j++) {
            int f   = tid + j * 128;
            int row = f >> 2;
            int kc  = (f & 3) << 2;
            cp16(&As[buf][row][kc], A + (size_t)(bm + row) * D_M + k0 + kc);
        }
        #pragma unroll
        for (int j = 0; j < 4; j++) {
            int f  = tid + j * 128;
            int kr = f >> 5;
            int nc = (f & 31) << 2;
            cp16(&Bs[buf][kr][nc], Wm + (size_t)(k0 + kr) * D_M + bn + nc);
        }
        CP_COMMIT();
    };

    int wid = tid >> 5, lane = tid & 31;
    int g = lane >> 2, cq = lane & 3;
    int wm = (wid & 1) * 64, wn = (wid >> 1) * 64;
    int nkt = (kend - kbeg) >> 4;

    load_stage(0, kbeg);

    for (int kt = 0; kt < nkt; kt++) {
        int buf = kt & 1;
        if (kt < nkt - 1) {
            load_stage(buf ^ 1, kbeg + (kt + 1) * 16);
            cp_wait<1>();
        } else {
            cp_wait<0>();
        }
        __syncthreads();

        #pragma unroll
        for (int ks = 0; ks < 2; ks++) {
            uint32_t af[4][4], bf[8][2];
            #pragma unroll
            for (int mi = 0; mi < 4; mi++) {
                int r0 = wm + mi * 16 + g;
                af[mi][0] = *(const uint32_t*)&As[buf][r0    ][ks * 8 + cq];
                af[mi][1] = *(const uint32_t*)&As[buf][r0 + 8][ks * 8 + cq];
                af[mi][2] = *(const uint32_t*)&As[buf][r0    ][ks * 8 + cq + 4];
                af[mi][3] = *(const uint32_t*)&As[buf][r0 + 8][ks * 8 + cq + 4];
            }
            #pragma unroll
            for (int ni = 0; ni < 8; ni++) {
                int c0 = wn + ni * 8 + g;
                bf[ni][0] = *(const uint32_t*)&Bs[buf][ks * 8 + cq    ][c0];
                bf[ni][1] = *(const uint32_t*)&Bs[buf][ks * 8 + cq + 4][c0];
            }
            #pragma unroll
            for (int mi = 0; mi < 4; mi++)
                #pragma unroll
                for (int ni = 0; ni < 8; ni++)
                    mma_tf32(acc[mi][ni], af[mi], bf[ni]);
        }
        __syncthreads();
    }
}

// ---------------------------------------------------------------------------
// Wc split-K partial: g_wcp[z] = Wx_r @ Ww_r over K slice z*256..+256.
// grid (8, 8, 4).
// ---------------------------------------------------------------------------
__global__ __launch_bounds__(128) void gemm_wc(void)
{
    __shared__ float As[2][128][20];
    __shared__ float Bs[2][16][136];

    const float* A  = g_wt + 4 * WM_SZ;   // Wx_r
    const float* Wm = g_wt + 5 * WM_SZ;   // Ww_r
    float*       C  = g_wcp + (size_t)blockIdx.z * WM_SZ;

    int tid = threadIdx.x;
    int bm = blockIdx.y * 128, bn = blockIdx.x * 128;
    int kbeg = blockIdx.z * 256;

    float acc[4][8][4];
    #pragma unroll
    for (int mi = 0; mi < 4; mi++)
        #pragma unroll
        for (int ni = 0; ni < 8; ni++)
            #pragma unroll
            for (int x = 0; x < 4; x++) acc[mi][ni][x] = 0.f;

    gemm_tile128(A, Wm, bm, bn, tid, acc, As, Bs, kbeg, kbeg + 256);

    int wid = tid >> 5, lane = tid & 31;
    int g = lane >> 2, cq = lane & 3;
    int wm = (wid & 1) * 64, wn = (wid >> 1) * 64;

    #pragma unroll
    for (int mi = 0; mi < 4; mi++) {
        int row0 = bm + wm + mi * 16 + g;
        #pragma unroll
        for (int ni = 0; ni < 8; ni++) {
            int col = bn + wn + ni * 8 + cq * 2;
            *(float2*)(C + (size_t)row0 * D_M + col)       = make_float2(acc[mi][ni][0], acc[mi][ni][1]);
            *(float2*)(C + (size_t)(row0 + 8) * D_M + col) = make_float2(acc[mi][ni][2], acc[mi][ni][3]);
        }
    }
}

// ---------------------------------------------------------------------------
// Wc reduce: sum 4 partials, round, write packed slab 3. grid 1024 x 256.
// ---------------------------------------------------------------------------
__global__ __launch_bounds__(256) void wc_reduce(void)
{
    size_t idx = ((size_t)blockIdx.x * 256 + threadIdx.x) * 4;
    size_t k = idx >> 10, c = idx & 1023;

    float4 a = *(const float4*)(g_wcp + idx);
    float4 b = *(const float4*)(g_wcp + WM_SZ + idx);
    float4 d = *(const float4*)(g_wcp + 2 * WM_SZ + idx);
    float4 e = *(const float4*)(g_wcp + 3 * WM_SZ + idx);
    float4 s;
    s.x = a.x + b.x + d.x + e.x;
    s.y = a.y + b.y + d.y + e.y;
    s.z = a.z + b.z + d.z + e.z;
    s.w = a.w + b.w + d.w + e.w;
    *(float4*)(g_wt + k * 4096 + 3 * D_M + c) = rnd4(s);
}

// ---------------------------------------------------------------------------
// Pass A: per-chunk local scan. grid (BH_N, CH_N), 512 threads.
// ---------------------------------------------------------------------------
__global__ __launch_bounds__(512) void scan_chunk_kernel()
{
    __shared__ float sk[CH_L][64], sw[CH_L][64], sr[CH_L][64], sv[CH_L][64];

    int bh = blockIdx.x, ch = blockIdx.y;
    int b = bh >> 4, h = bh & 15;
    int tid = threadIdx.x;
    int e = tid >> 3, dq = tid & 7;

    size_t base = (size_t)b * T_N * D_M + (size_t)ch * CH_L * D_M + h * HS_N;

    {
        int t = tid >> 4, c = (tid & 15) * 4;
        size_t off = base + (size_t)t * D_M + c;
        cp16(&sk[t][c], g_k + off);
        cp16(&sw[t][c], g_w + off);
        cp16(&sr[t][c], g_r + off);
        cp16(&sv[t][c], g_v + off);
    }
    CP_COMMIT();
    cp_wait<0>();
    __syncthreads();

    float s[8], cum[8];
    #pragma unroll
    for (int i = 0; i < 8; i++) { s[i] = 0.f; cum[i] = 1.f; }

    float* op = g_o + base + e;
    float* qp = g_r + base + dq * 8;

    for (int t = 0; t < CH_L; t++) {
        float4 k0 = *(const float4*)&sk[t][dq * 8];
        float4 k1 = *(const float4*)&sk[t][dq * 8 + 4];
        float4 w0 = *(const float4*)&sw[t][dq * 8];
        float4 w1 = *(const float4*)&sw[t][dq * 8 + 4];
        float4 r0 = *(const float4*)&sr[t][dq * 8];
        float4 r1 = *(const float4*)&sr[t][dq * 8 + 4];
        float vv  = sv[t][e];

        float kc[8] = {k0.x, k0.y, k0.z, k0.w, k1.x, k1.y, k1.z, k1.w};
        float wc[8] = {w0.x, w0.y, w0.z, w0.w, w1.x, w1.y, w1.z, w1.w};
        float rc[8] = {r0.x, r0.y, r0.z, r0.w, r1.x, r1.y, r1.z, r1.w};

        float acc = 0.f;
        #pragma unroll
        for (int i = 0; i < 8; i++) {
            float omw = 1.f - wc[i];
            cum[i] *= omw;
            float si = fmaf(kc[i], vv, s[i] * omw);
            s[i] = si;
            acc = fmaf(rc[i], si, acc);
        }
        acc += __shfl_xor_sync(0xffffffffu, acc, 1);
        acc += __shfl_xor_sync(0xffffffffu, acc, 2);
        acc += __shfl_xor_sync(0xffffffffu, acc, 4);
        if (dq == 0) *op = acc;
        op += D_M;

        if (e == 0) {
            float q[8];
            #pragma unroll
            for (int i = 0; i < 8; i++) q[i] = rc[i] * cum[i];
            *(float4*)(qp)     = make_float4(q[0], q[1], q[2], q[3]);
            *(float4*)(qp + 4) = make_float4(q[4], q[5], q[6], q[7]);
        }
        qp += D_M;
    }

    size_t sb = ((size_t)bh * CH_N + ch) * (HS_N * HS_N) + (size_t)e * HS_N + dq * 8;
    *(float4*)(g_sloc + sb)     = make_float4(s[0], s[1], s[2], s[3]);
    *(float4*)(g_sloc + sb + 4) = make_float4(s[4], s[5], s[6], s[7]);

    if (e == 0) {
        size_t pb = ((size_t)bh * CH_N + ch) * HS_N + dq * 8;
        *(float4*)(g_pc + pb)     = make_float4(cum[0], cum[1], cum[2], cum[3]);
        *(float4*)(g_pc + pb + 4) = make_float4(cum[4], cum[5], cum[6], cum[7]);
    }
}

// ---------------------------------------------------------------------------
// Pass B: parallel chunk combine. grid (BH_N, 8), 512 threads.
// ---------------------------------------------------------------------------
__global__ __launch_bounds__(512) void combine_kernel(float* __restrict__ Sout)
{
    int bh = blockIdx.x;
    int eg = blockIdx.y;
    int tid = threadIdx.x;
    int e = eg * 8 + (tid >> 6);
    int d = tid & 63;

    size_t sbase = (size_t)bh * CH_N * (HS_N * HS_N) + (size_t)e * HS_N + d;
    size_t pbase = (size_t)bh * CH_N * HS_N + d;

    float carry = 0.f;
    #pragma unroll 4
    for (int ch = 0; ch < CH_N; ch++) {
        float pc = g_pc[pbase + (size_t)ch * HS_N];
        float sl = g_sloc[sbase + (size_t)ch * (HS_N * HS_N)];
        g_sin[sbase + (size_t)ch * (HS_N * HS_N)] = carry;
        carry = fmaf(pc, carry, sl);
    }

    Sout[(size_t)bh * (HS_N * HS_N) + (size_t)d * HS_N + e] = carry;
}

// ---------------------------------------------------------------------------
// Pass C: out_t += q_t . s_in[ch]; round to tf32. grid (BH_N, CH_N), 256 thr.
// ---------------------------------------------------------------------------
__global__ __launch_bounds__(256) void corr_kernel()
{
    __shared__ float sq[CH_L][64];
    __shared__ float sS[64][68];

    int bh = blockIdx.x, ch = blockIdx.y;
    int b = bh >> 4, h = bh & 15;
    int tid = threadIdx.x;

    size_t qbase = (size_t)b * T_N * D_M + (size_t)ch * CH_L * D_M + h * HS_N;
    size_t sbase = ((size_t)bh * CH_N + ch) * (HS_N * HS_N);

    #pragma unroll
    for (int j = 0; j < 2; j++) {
        int f = tid + j * 256;
        int t = f >> 4, c = (f & 15) * 4;
        cp16(&sq[t][c], g_r + qbase + (size_t)t * D_M + c);
    }
    #pragma unroll
    for (int j = 0; j < 4; j++) {
        int f = tid + j * 256;
        int ee = f >> 4, d = (f & 15) * 4;
        cp16(&sS[ee][d], g_sin + sbase + (size_t)ee * HS_N + d);
    }
    CP_COMMIT();
    cp_wait<0>();
    __syncthreads();

    int tg = tid >> 5;
    int el = tid & 31;

    float a[4][2];
    #pragma unroll
    for (int j = 0; j < 4; j++) { a[j][0] = 0.f; a[j][1] = 0.f; }

    for (int d0 = 0; d0 < 64; d0 += 4) {
        float4 s0 = *(const float4*)&sS[el][d0];
        float4 s1 = *(const float4*)&sS[el + 32][d0];
        #pragma unroll
        for (int j = 0; j < 4; j++) {
            float4 qv = *(const float4*)&sq[tg * 4 + j][d0];
            a[j][0] = fmaf(qv.x, s0.x, fmaf(qv.y, s0.y, fmaf(qv.z, s0.z, fmaf(qv.w, s0.w, a[j][0]))));
            a[j][1] = fmaf(qv.x, s1.x, fmaf(qv.y, s1.y, fmaf(qv.z, s1.z, fmaf(qv.w, s1.w, a[j][1]))));
        }
    }

    #pragma unroll
    for (int j = 0; j < 4; j++) {
        float* p0 = g_o + qbase + (size_t)(tg * 4 + j) * D_M + el;
        float* p1 = p0 + 32;
        *p0 = to_tf32f(*p0 + a[j][0]);
        *p1 = to_tf32f(*p1 + a[j][1]);
    }
}

// ---------------------------------------------------------------------------
// Launch — kernel launches ONLY (graph-capture safe)
// ---------------------------------------------------------------------------
extern "C" void kernel_launch(void* const* d_in, const int* in_sizes, int n_in,
                              void* d_out, int out_size)
{
    const float* x    = (const float*)d_in[0];
    const float* ln_g = (const float*)d_in[1];
    const float* ln_b = (const float*)d_in[2];
    const float* Wx   = (const float*)d_in[3];
    const float* Ww   = (const float*)d_in[4];
    const float* bw   = (const float*)d_in[5];
    const float* Wk   = (const float*)d_in[6];
    const float* Wv   = (const float*)d_in[7];
    const float* Wr   = (const float*)d_in[8];
    const float* Wo   = (const float*)d_in[9];
    float* out = (float*)d_out;

    // 0) round + pack weights
    round_w_kernel<<<1024, 256>>>(Wx, Ww, Wk, Wv, Wr, Wo);

    // 0b) Wc = Wx_r @ Ww_r via split-K x4 (256 blocks) + reduce into slab 3
    gemm_wc<<<dim3(8, 8, 4), 128>>>();
    wc_reduce<<<1024, 256>>>();

    // 1) LayerNorm -> g_xn (rounded)
    ln_kernel<<<MROWS, 256>>>(x, ln_g, ln_b);

    // 2) Fused projections: k, v, r=sig, w=sig(+bw)  (2048 blocks, 256 thr)
    gemm_fused<<<dim3(32, 64), 256>>>(bw);

    // 3) Chunked parallel scan
    scan_chunk_kernel<<<dim3(BH_N, CH_N), 512>>>();
    combine_kernel<<<dim3(BH_N, 8), 512>>>(out + (size_t)MROWS * D_M);
    corr_kernel<<<dim3(BH_N, CH_N), 256>>>();

    // 4) y = o @ Wo -> head of d_out  (512 blocks, 256 thr)
    gemm_out<<<dim3(8, 64), 256>>>(out);
}